// round 2
// baseline (speedup 1.0000x reference)
#include <cuda_runtime.h>
#include <stdint.h>

#define CC   128
#define CI   32
#define HH   128
#define WW   256
#define BB   8
#define HW   (HH*WW)

// Precomputed parameters (filled by prep kernel each launch; deterministic).
__device__ uint32_t g_w1m[CI][4];
__device__ float    g_inv1[CI], g_bb1[CI];
__device__ uint32_t g_w2m[CI][9];
__device__ float    g_inv2[CI], g_bb2[CI];
__device__ uint32_t g_w3m[CC];
__device__ float    g_inv3[CC], g_bb3[CC];

// Scratch: h1 binarized activations, 32 channels packed per pixel. 1 MB.
__device__ uint32_t g_h1b[BB * HW];

// ---------------------------------------------------------------------------
// Prep: binarize weights into bitmasks, fold BN into (inv, bb).
// bit c = (w > 0)  <=>  binarize(w) == +1   (w <= 0 -> -1)
// bn(z) = z*inv + bb,  inv = g/sqrt(v+eps) > 0,  bb = b - m*inv
// ---------------------------------------------------------------------------
__global__ void prep_kernel(
    const float* __restrict__ w1, const float* __restrict__ g1,
    const float* __restrict__ b1, const float* __restrict__ m1, const float* __restrict__ v1,
    const float* __restrict__ w2, const float* __restrict__ g2,
    const float* __restrict__ b2, const float* __restrict__ m2, const float* __restrict__ v2,
    const float* __restrict__ w3, const float* __restrict__ g3,
    const float* __restrict__ b3, const float* __restrict__ m3, const float* __restrict__ v3)
{
    int t = threadIdx.x;  // 128 threads
    if (t < CI) {
        // w1: [CI][CC] 1x1
        #pragma unroll
        for (int j = 0; j < 4; j++) {
            uint32_t m = 0;
            for (int i = 0; i < 32; i++)
                if (w1[t * CC + j * 32 + i] > 0.f) m |= (1u << i);
            g_w1m[t][j] = m;
        }
        float inv = __fdiv_rn(g1[t], __fsqrt_rn(__fadd_rn(v1[t], 1e-5f)));
        g_inv1[t] = inv;
        g_bb1[t]  = __fadd_rn(b1[t], -__fmul_rn(m1[t], inv));

        // w2: [CI][CI][3][3]
        for (int t9 = 0; t9 < 9; t9++) {
            uint32_t m = 0;
            for (int i = 0; i < 32; i++)
                if (w2[t * (CI * 9) + i * 9 + t9] > 0.f) m |= (1u << i);
            g_w2m[t][t9] = m;
        }
        inv = __fdiv_rn(g2[t], __fsqrt_rn(__fadd_rn(v2[t], 1e-5f)));
        g_inv2[t] = inv;
        g_bb2[t]  = __fadd_rn(b2[t], -__fmul_rn(m2[t], inv));
    }
    if (t < CC) {
        // w3: [CC][CI] 1x1
        uint32_t m = 0;
        for (int i = 0; i < 32; i++)
            if (w3[t * CI + i] > 0.f) m |= (1u << i);
        g_w3m[t] = m;
        float inv = __fdiv_rn(g3[t], __fsqrt_rn(__fadd_rn(v3[t], 1e-5f)));
        g_inv3[t] = inv;
        g_bb3[t]  = __fadd_rn(b3[t], -__fmul_rn(m3[t], inv));
    }
}

// ---------------------------------------------------------------------------
// Kernel A: conv1 (1x1, 128->32) + bn + sign  -> packed h1 bitmask per pixel.
// One thread per pixel; channel loop is coalesced across the warp (W-contig).
// ---------------------------------------------------------------------------
__global__ void __launch_bounds__(256) k_conv1(const float* __restrict__ x)
{
    __shared__ uint32_t sw1[CI][4];
    __shared__ float sinv1[CI], sbb1[CI];
    int tid = threadIdx.x;
    if (tid < CI) {
        sinv1[tid] = g_inv1[tid]; sbb1[tid] = g_bb1[tid];
        #pragma unroll
        for (int j = 0; j < 4; j++) sw1[tid][j] = g_w1m[tid][j];
    }
    __syncthreads();

    int px = blockIdx.x * 256 + tid;        // 0 .. B*H*W-1 (exact multiple)
    int b  = px / HW;
    int p  = px - b * HW;
    const float* xp = x + (size_t)b * (CC * HW) + p;

    uint32_t s0 = 0, s1 = 0, s2 = 0, s3 = 0;
    #pragma unroll
    for (int i = 0; i < 32; i++) {
        if (xp[(i      ) * HW] > 0.f) s0 |= (1u << i);
        if (xp[(i +  32) * HW] > 0.f) s1 |= (1u << i);
        if (xp[(i +  64) * HW] > 0.f) s2 |= (1u << i);
        if (xp[(i +  96) * HW] > 0.f) s3 |= (1u << i);
    }

    uint32_t outm = 0;
    #pragma unroll
    for (int oc = 0; oc < CI; oc++) {
        int pc = __popc(s0 ^ sw1[oc][0]) + __popc(s1 ^ sw1[oc][1])
               + __popc(s2 ^ sw1[oc][2]) + __popc(s3 ^ sw1[oc][3]);
        float z = (float)(128 - 2 * pc);
        float v = __fadd_rn(__fmul_rn(z, sinv1[oc]), sbb1[oc]);
        if (v > 0.f) outm |= (1u << oc);   // bit set <=> binarized +1
    }
    g_h1b[px] = outm;
}

// ---------------------------------------------------------------------------
// Kernel B: conv2 (3x3, zero-padded AFTER binarize -> per-tap validity)
//           + conv3 (1x1, 32->128) + bn + prelu + residual + prelu.
// Tile 32(W) x 8(H), one thread per pixel.
// ---------------------------------------------------------------------------
#define TW 32
#define TH 8

__global__ void __launch_bounds__(256) k_main(
    const float* __restrict__ x, float* __restrict__ out,
    const float* __restrict__ a3p, const float* __restrict__ aoutp)
{
    __shared__ uint32_t sh1[TH + 2][TW + 2];
    __shared__ uint32_t sw2[CI][9];
    __shared__ float sinv2[CI], sbb2[CI];
    __shared__ uint32_t sw3[CC];
    __shared__ float sinv3[CC], sbb3[CC];

    int tid = threadIdx.x;
    int tx = tid & (TW - 1);
    int ty = tid / TW;
    int w0 = blockIdx.x * TW;
    int h0 = blockIdx.y * TH;
    int b  = blockIdx.z;

    if (tid < CC) { sw3[tid] = g_w3m[tid]; sinv3[tid] = g_inv3[tid]; sbb3[tid] = g_bb3[tid]; }
    if (tid < CI) {
        sinv2[tid] = g_inv2[tid]; sbb2[tid] = g_bb2[tid];
        #pragma unroll
        for (int t9 = 0; t9 < 9; t9++) sw2[tid][t9] = g_w2m[tid][t9];
    }

    // Load h1 bitmask tile + 1-pixel halo
    const uint32_t* h1b = g_h1b + (size_t)b * HW;
    for (int it = tid; it < (TH + 2) * (TW + 2); it += 256) {
        int hy = it / (TW + 2), hx = it - hy * (TW + 2);
        int gh = h0 + hy - 1, gw = w0 + hx - 1;
        uint32_t v = 0;
        if (gh >= 0 && gh < HH && gw >= 0 && gw < WW) v = h1b[gh * WW + gw];
        sh1[hy][hx] = v;
    }
    __syncthreads();

    int gh = h0 + ty, gw = w0 + tx;

    // conv2: gather 9 neighbor masks; taps outside the image contribute 0.
    uint32_t n[9];
    bool ok[9];
    #pragma unroll
    for (int t = 0; t < 9; t++) {
        int dy = t / 3 - 1, dx = t % 3 - 1;
        int yy = gh + dy, xx = gw + dx;
        ok[t] = (yy >= 0) & (yy < HH) & (xx >= 0) & (xx < WW);
        n[t] = sh1[ty + 1 + dy][tx + 1 + dx];
    }

    uint32_t h2b = 0;
    #pragma unroll
    for (int oc = 0; oc < CI; oc++) {
        int z = 0;
        #pragma unroll
        for (int t = 0; t < 9; t++) {
            int c9 = 32 - 2 * __popc(n[t] ^ sw2[oc][t]);
            z += ok[t] ? c9 : 0;
        }
        float v = __fadd_rn(__fmul_rn((float)z, sinv2[oc]), sbb2[oc]);
        if (v > 0.f) h2b |= (1u << oc);
    }

    // conv3 + bn + prelu + residual + prelu (streams x and out once)
    float a3   = a3p[0];
    float aout = aoutp[0];
    size_t base = (size_t)b * (CC * HW) + (size_t)gh * WW + gw;
    const float* xp = x + base;
    float* op = out + base;

    #pragma unroll 16
    for (int c = 0; c < CC; c++) {
        int z = 32 - 2 * __popc(h2b ^ sw3[c]);
        float v = __fadd_rn(__fmul_rn((float)z, sinv3[c]), sbb3[c]);
        v = (v >= 0.f) ? v : a3 * v;
        float s = v + xp[(size_t)c * HW];
        s = (s >= 0.f) ? s : aout * s;
        op[(size_t)c * HW] = s;
    }
}

// ---------------------------------------------------------------------------
extern "C" void kernel_launch(void* const* d_in, const int* in_sizes, int n_in,
                              void* d_out, int out_size)
{
    const float* x  = (const float*)d_in[0];
    const float* w1 = (const float*)d_in[1];
    const float* g1 = (const float*)d_in[2];
    const float* b1 = (const float*)d_in[3];
    const float* m1 = (const float*)d_in[4];
    const float* v1 = (const float*)d_in[5];
    // d_in[6] = a1 (unused: prelu with a>0 never changes the following sign)
    const float* w2 = (const float*)d_in[7];
    const float* g2 = (const float*)d_in[8];
    const float* b2 = (const float*)d_in[9];
    const float* m2 = (const float*)d_in[10];
    const float* v2 = (const float*)d_in[11];
    // d_in[12] = a2 (unused, same reason)
    const float* w3 = (const float*)d_in[13];
    const float* g3 = (const float*)d_in[14];
    const float* b3 = (const float*)d_in[15];
    const float* m3 = (const float*)d_in[16];
    const float* v3 = (const float*)d_in[17];
    const float* a3 = (const float*)d_in[18];
    const float* ao = (const float*)d_in[19];
    float* out = (float*)d_out;

    prep_kernel<<<1, 128>>>(w1, g1, b1, m1, v1,
                            w2, g2, b2, m2, v2,
                            w3, g3, b3, m3, v3);

    k_conv1<<<(BB * HW) / 256, 256>>>(x);

    dim3 grid(WW / TW, HH / TH, BB);
    k_main<<<grid, 256>>>(x, out, a3, ao);
}